// round 15
// baseline (speedup 1.0000x reference)
#include <cuda_runtime.h>
#include <cuda_fp16.h>
#include <math.h>
#include <stdint.h>

// Problem constants
#define N_NODES   10000
#define N_EDGES   160000
#define IN_FEATS  512
#define HEADS     8
#define OUT_FEATS 64
#define HF        (HEADS * OUT_FEATS)   // 512
#define NEG_SLOPE 0.2f

// ---------------- scratch (device globals; no allocs allowed) ----------------
// NOTE: zero-initialized at load; aggregate_kernel re-zeros the counters it
// consumed so every graph replay sees identical initial state.
__device__ float g_hf[N_NODES * HF];         // projected features, fp32
__device__ float g_el[N_NODES * HEADS];
__device__ float g_er[N_NODES * HEADS];
__device__ int   g_cnt[N_NODES + 1];
__device__ int   g_off[N_NODES + 1];
__device__ int   g_cur[N_NODES];
__device__ int   g_srcp[N_EDGES];            // src*HF per CSR slot
__device__ float g_e[N_EDGES * HEADS];       // leaky logits per CSR slot
__device__ int   g_tile;
__device__ __half g_W16[HF * IN_FEATS];      // W^T fp16: [n][k]
__device__ __half g_Ah16[N_NODES * IN_FEATS]; // feat fp16 hi: [m][k]
__device__ __half g_Al16[N_NODES * IN_FEATS]; // feat fp16 lo: [m][k]

// ------------------------------ PTX helpers ----------------------------------
__device__ __forceinline__ uint32_t smem_u32(const void* p) {
    uint32_t a;
    asm("{ .reg .u64 t; cvta.to.shared.u64 t, %1; cvt.u32.u64 %0, t; }"
        : "=r"(a) : "l"(p));
    return a;
}
__device__ __forceinline__ void cp_async16(uint32_t sa, const void* gp) {
    asm volatile("cp.async.cg.shared.global [%0], [%1], 16;"
                 :: "r"(sa), "l"(gp));
}
__device__ __forceinline__ void cp_async16z(uint32_t sa, const void* gp, int sz) {
    asm volatile("cp.async.cg.shared.global [%0], [%1], 16, %2;"
                 :: "r"(sa), "l"(gp), "r"(sz));
}
__device__ __forceinline__ void cp_commit() {
    asm volatile("cp.async.commit_group;" ::: "memory");
}
template <int N>
__device__ __forceinline__ void cp_wait() {
    asm volatile("cp.async.wait_group %0;" :: "n"(N) : "memory");
}
__device__ __forceinline__ void ldsm4(uint32_t* r, uint32_t addr) {
    asm volatile("ldmatrix.sync.aligned.m8n8.x4.shared.b16 {%0,%1,%2,%3}, [%4];"
                 : "=r"(r[0]), "=r"(r[1]), "=r"(r[2]), "=r"(r[3]) : "r"(addr));
}
__device__ __forceinline__ void mma16816(float* d, const uint32_t* a, const uint32_t* b) {
    asm volatile(
        "mma.sync.aligned.m16n8k16.row.col.f32.f16.f16.f32 "
        "{%0,%1,%2,%3}, {%4,%5,%6,%7}, {%8,%9}, {%0,%1,%2,%3};"
        : "+f"(d[0]), "+f"(d[1]), "+f"(d[2]), "+f"(d[3])
        : "r"(a[0]), "r"(a[1]), "r"(a[2]), "r"(a[3]), "r"(b[0]), "r"(b[1]));
}

// ===== pre-pass: feat fp16 hi/lo split + CSR edge count + W transpose =========
__global__ __launch_bounds__(256) void asplit_w_kernel(
    const float* __restrict__ feat, const float* __restrict__ W,
    const int* __restrict__ dst)
{
    int tid = threadIdx.x;

    // fused edge counting on the first 625 blocks
    int eid = blockIdx.x * 256 + tid;
    if (eid < N_EDGES) atomicAdd(&g_cnt[dst[eid]], 1);

    // W transpose on blocks 0..255
    __shared__ float tile[32][33];
    if (blockIdx.x < 256) {
        int bx = blockIdx.x & 15;   // n tile
        int by = blockIdx.x >> 4;   // k tile
        int tx = tid & 31;
        int ty = tid >> 5;
        for (int i = ty; i < 32; i += 8)
            tile[i][tx] = W[(by * 32 + i) * HF + bx * 32 + tx];
        __syncthreads();
        int k = by * 32 + tx;
        for (int i = ty; i < 32; i += 8) {
            int n = bx * 32 + i;
            g_W16[n * IN_FEATS + k] = __float2half_rn(tile[tx][i]);
        }
    }

    // feat split: one float4 per thread
    int i = blockIdx.x * 256 + tid;
    if (i >= N_NODES * IN_FEATS / 4) return;
    float4 v = ((const float4*)feat)[i];
    float f[4] = {v.x, v.y, v.z, v.w};
    __half h[4], lo[4];
    #pragma unroll
    for (int j = 0; j < 4; ++j) {
        h[j]  = __float2half_rn(f[j]);
        lo[j] = __float2half_rn(f[j] - __half2float(h[j]));
    }
    ((uint2*)g_Ah16)[i] = make_uint2(
        ((uint32_t)__half_as_ushort(h[1]) << 16) | __half_as_ushort(h[0]),
        ((uint32_t)__half_as_ushort(h[3]) << 16) | __half_as_ushort(h[2]));
    ((uint2*)g_Al16)[i] = make_uint2(
        ((uint32_t)__half_as_ushort(lo[1]) << 16) | __half_as_ushort(lo[0]),
        ((uint32_t)__half_as_ushort(lo[3]) << 16) | __half_as_ushort(lo[2]));
}

// ============== persistent HMMA fp16x2 GEMM + fused el/er + scan ==============
#define BM 64
#define BN 128
#define BK 32
#define NCH (IN_FEATS / BK)        // 16
#define ROWB 80                    // 64B data + 16B pad
#define AH_OFF 0
#define AL_OFF (BM * ROWB)               // 5120
#define B_OFF  (2 * BM * ROWB)           // 10240
#define STAGE_BYTES (B_OFF + BN * ROWB)  // 20480
#define SM_TOTAL (3 * STAGE_BYTES)       // 61440
#define MT_TILES 157
#define NT_TILES 4
#define NTILES (MT_TILES * NT_TILES)     // 628
#define GRID_GEMM 444
#define SCAN_CHUNK 40                    // 256 threads x 40 >= 10001

__global__ __launch_bounds__(256, 3) void gemm_hmma_kernel(
    const float* __restrict__ attn_l,
    const float* __restrict__ attn_r)
{
    extern __shared__ char smem[];
    __shared__ int sh_tile;
    uint32_t sb = smem_u32(smem);
    int tid = threadIdx.x;
    int w = tid >> 5;
    int l = tid & 31;
    int wm = (w >> 2) * 32;
    int wn = (w & 3) * 32;
    int lr = l & 15;
    int kc = (l & 16) ? 8 : 0;

    // ---- block 0: CSR exclusive scan (two-pass, L2-resident g_cnt) ----
    if (blockIdx.x == 0) {
        int* ssum = (int*)smem;
        int base = tid * SCAN_CHUNK;
        int s = 0;
        for (int j = 0; j < SCAN_CHUNK; ++j) {
            int idx = base + j;
            if (idx < N_NODES) s += g_cnt[idx];
        }
        ssum[tid] = s;
        __syncthreads();
        for (int d = 1; d < 256; d <<= 1) {
            int add = (tid >= d) ? ssum[tid - d] : 0;
            __syncthreads();
            ssum[tid] += add;
            __syncthreads();
        }
        int run = ssum[tid] - s;
        for (int j = 0; j < SCAN_CHUNK; ++j) {
            int idx = base + j;
            if (idx <= N_NODES) {
                g_off[idx] = run;
                if (idx < N_NODES) run += g_cnt[idx];
            }
        }
        __syncthreads();
    }

    uint32_t aoff0 = (uint32_t)(wm + lr) * ROWB;
    uint32_t aoff1 = (uint32_t)(wm + 16 + lr) * ROWB;
    uint32_t boff0 = (uint32_t)(wn + lr) * ROWB;
    uint32_t boff1 = (uint32_t)(wn + 16 + lr) * ROWB;
    int arow = tid >> 2;
    int ac16 = tid & 3;
    int brow0 = tid >> 1;
    int bseg = (tid & 1) * 2;

    for (;;) {
        if (tid == 0) sh_tile = atomicAdd(&g_tile, 1);
        __syncthreads();
        int t = sh_tile;
        if (t >= NTILES) break;
        int bm = (t >> 2) * BM;
        int bn = (t & 3) * BN;

        float acc[2][4][4];
        #pragma unroll
        for (int a = 0; a < 2; ++a)
            #pragma unroll
            for (int b = 0; b < 4; ++b)
                #pragma unroll
                for (int c = 0; c < 4; ++c) acc[a][b][c] = 0.f;

        int agrow = bm + arow;
        int asz = (agrow < N_NODES) ? 16 : 0;
        if (agrow >= N_NODES) agrow = 0;
        const __half* apH = g_Ah16 + (size_t)agrow * IN_FEATS + ac16 * 8;
        const __half* apL = g_Al16 + (size_t)agrow * IN_FEATS + ac16 * 8;
        const __half* bp0 = g_W16 + (size_t)(bn + brow0) * IN_FEATS + bseg * 8;
        uint32_t sA = (uint32_t)arow * ROWB + ac16 * 16;
        uint32_t sB = (uint32_t)brow0 * ROWB + bseg * 16;

        auto load_chunk = [&](int c) {
            int k0 = c * BK;
            uint32_t st = sb + (c % 3) * STAGE_BYTES;
            cp_async16z(st + AH_OFF + sA, apH + k0, asz);
            cp_async16z(st + AL_OFF + sA, apL + k0, asz);
            cp_async16(st + B_OFF + sB,      bp0 + k0);
            cp_async16(st + B_OFF + sB + 16, bp0 + k0 + 8);
            cp_commit();
        };

        load_chunk(0);
        load_chunk(1);

        for (int c = 0; c < NCH; ++c) {
            if (c < NCH - 1) cp_wait<1>(); else cp_wait<0>();
            __syncthreads();
            if (c + 2 < NCH) load_chunk(c + 2);

            uint32_t st = sb + (c % 3) * STAGE_BYTES;
            uint32_t sA_h = st + AH_OFF;
            uint32_t sA_l = st + AL_OFF;
            uint32_t sB_h = st + B_OFF;

            #pragma unroll
            for (int ks = 0; ks < 2; ++ks) {
                uint32_t koff = (ks * 16 + kc) * 2;
                uint32_t bf[4][2];
                {
                    uint32_t r[4];
                    ldsm4(r, sB_h + boff0 + koff);
                    bf[0][0] = r[0]; bf[1][0] = r[1];
                    bf[0][1] = r[2]; bf[1][1] = r[3];
                    ldsm4(r, sB_h + boff1 + koff);
                    bf[2][0] = r[0]; bf[3][0] = r[1];
                    bf[2][1] = r[2]; bf[3][1] = r[3];
                }
                uint32_t ahf[2][4], alf[2][4];
                ldsm4(ahf[0], sA_h + aoff0 + koff);
                ldsm4(ahf[1], sA_h + aoff1 + koff);
                ldsm4(alf[0], sA_l + aoff0 + koff);
                ldsm4(alf[1], sA_l + aoff1 + koff);
                #pragma unroll
                for (int fm = 0; fm < 2; ++fm)
                    #pragma unroll
                    for (int fn = 0; fn < 4; ++fn)
                        mma16816(acc[fm][fn], ahf[fm], bf[fn]);
                #pragma unroll
                for (int fm = 0; fm < 2; ++fm)
                    #pragma unroll
                    for (int fn = 0; fn < 4; ++fn)
                        mma16816(acc[fm][fn], alf[fm], bf[fn]);
            }
        }

        // ---- epilogue 1: h stores (fp32) ----
        #pragma unroll
        for (int fm = 0; fm < 2; ++fm) {
            int r0 = bm + wm + fm * 16 + (l >> 2);
            int r1 = r0 + 8;
            #pragma unroll
            for (int fn = 0; fn < 4; ++fn) {
                int col = bn + wn + fn * 8 + (l & 3) * 2;
                if (r0 < N_NODES)
                    *(float2*)(g_hf + (size_t)r0 * HF + col) =
                        make_float2(acc[fm][fn][0], acc[fm][fn][1]);
                if (r1 < N_NODES)
                    *(float2*)(g_hf + (size_t)r1 * HF + col) =
                        make_float2(acc[fm][fn][2], acc[fm][fn][3]);
            }
        }

        // ---- epilogue 2: fused el/er (deterministic) ----
        float* pel = (float*)smem;
        float* per = (float*)smem + BM * 4;
        float avl[8], avr[8];
        #pragma unroll
        for (int fn = 0; fn < 4; ++fn) {
            int colg = bn + wn + fn * 8 + (l & 3) * 2;
            avl[2*fn]   = attn_l[colg];
            avl[2*fn+1] = attn_l[colg + 1];
            avr[2*fn]   = attn_r[colg];
            avr[2*fn+1] = attn_r[colg + 1];
        }
        int wnidx = w & 3;
        __syncthreads();
        #pragma unroll
        for (int fm = 0; fm < 2; ++fm) {
            float pl0 = 0.f, pl1 = 0.f, pr0 = 0.f, pr1 = 0.f;
            #pragma unroll
            for (int fn = 0; fn < 4; ++fn) {
                pl0 += acc[fm][fn][0] * avl[2*fn] + acc[fm][fn][1] * avl[2*fn+1];
                pl1 += acc[fm][fn][2] * avl[2*fn] + acc[fm][fn][3] * avl[2*fn+1];
                pr0 += acc[fm][fn][0] * avr[2*fn] + acc[fm][fn][1] * avr[2*fn+1];
                pr1 += acc[fm][fn][2] * avr[2*fn] + acc[fm][fn][3] * avr[2*fn+1];
            }
            #pragma unroll
            for (int o = 1; o <= 2; o <<= 1) {
                pl0 += __shfl_xor_sync(0xFFFFFFFFu, pl0, o);
                pl1 += __shfl_xor_sync(0xFFFFFFFFu, pl1, o);
                pr0 += __shfl_xor_sync(0xFFFFFFFFu, pr0, o);
                pr1 += __shfl_xor_sync(0xFFFFFFFFu, pr1, o);
            }
            if ((l & 3) == 0) {
                int lr0 = wm + fm * 16 + (l >> 2);
                int lr1 = lr0 + 8;
                pel[lr0 * 4 + wnidx] = pl0;
                pel[lr1 * 4 + wnidx] = pl1;
                per[lr0 * 4 + wnidx] = pr0;
                per[lr1 * 4 + wnidx] = pr1;
            }
        }
        __syncthreads();
        if (tid < 2 * BM) {
            int row = tid >> 1;
            int tt = tid & 1;
            int grow = bm + row;
            if (grow < N_NODES) {
                float el = pel[row * 4 + 2 * tt] + pel[row * 4 + 2 * tt + 1];
                float er = per[row * 4 + 2 * tt] + per[row * 4 + 2 * tt + 1];
                int hd = (t & 3) * 2 + tt;
                g_el[grow * HEADS + hd] = el;
                g_er[grow * HEADS + hd] = er;
            }
        }
        __syncthreads();
    }
}

// -------- fill CSR slots + CSR-ordered leaky logits, 2 threads/edge ----------
__global__ __launch_bounds__(512) void fill_logits_kernel(
    const int* __restrict__ src, const int* __restrict__ dst)
{
    int tid = threadIdx.x;
    int e = blockIdx.x * 256 + (tid >> 1);      // exactly covers 160000
    int half = tid & 1;
    int lane = tid & 31;

    int d = dst[e];
    int s = src[e];
    int slot = 0;
    if (half == 0) slot = atomicAdd(&g_cur[d], 1);
    slot = __shfl_sync(0xFFFFFFFFu, slot, lane & ~1);
    int i = g_off[d] + slot;
    if (half == 0) g_srcp[i] = s * HF;          // pre-scaled row offset

    float4 lv = *(const float4*)&g_el[s * HEADS + half * 4];
    float4 rv = *(const float4*)&g_er[d * HEADS + half * 4];
    float v0 = lv.x + rv.x, v1 = lv.y + rv.y, v2 = lv.z + rv.z, v3 = lv.w + rv.w;
    v0 = (v0 > 0.f) ? v0 : NEG_SLOPE * v0;
    v1 = (v1 > 0.f) ? v1 : NEG_SLOPE * v1;
    v2 = (v2 > 0.f) ? v2 : NEG_SLOPE * v2;
    v3 = (v3 > 0.f) ? v3 : NEG_SLOPE * v3;
    *(float4*)&g_e[i * HEADS + half * 4] = make_float4(v0, v1, v2, v3);
}

// ---------- softmax (no max shift; logits bounded) + aggregation -------------
// One block/node, one warp/head. 4 edges per warp-iteration via 2x LDG.128
// fp32 (no cvts): g = lane>>3 picks edge in quad, fl = lane&7 picks octet.
__global__ __launch_bounds__(256) void aggregate_kernel(
    const float* __restrict__ bias,
    float* __restrict__ out)
{
    __shared__ float2 buf[8][32];   // (p, srcHF-as-int) per warp
    int n = blockIdx.x;

    if (threadIdx.x == 0) {
        g_cur[n] = 0;
        g_cnt[n] = 0;
        if (n == 0) { g_cnt[N_NODES] = 0; g_tile = 0; }
    }

    int hd = threadIdx.x >> 5;
    int lane = threadIdx.x & 31;
    int g = lane >> 3;          // 0..3 (edge in quad)
    int fl = lane & 7;          // 0..7 (feature octet)
    int fofs = hd * OUT_FEATS + fl * 8;

    int beg = g_off[n];
    int end = g_off[n + 1];

    float ssum = 0.f;
    float acc[8];
    #pragma unroll
    for (int q = 0; q < 8; ++q) acc[q] = 0.f;

    for (int base = beg; base < end; base += 32) {
        int cnt = end - base; if (cnt > 32) cnt = 32;
        if (lane < cnt) {
            int i = base + lane;
            float p = __expf(g_e[i * HEADS + hd]);   // no shift: |e| <~ 10
            ssum += p;
            buf[hd][lane] = make_float2(p, __int_as_float(g_srcp[i]));
        }
        __syncwarp();
        if (cnt == 32) {
            #pragma unroll
            for (int j = 0; j < 32; j += 4) {
                float2 ps = buf[hd][j + g];
                const float4* hp = (const float4*)(g_hf + __float_as_int(ps.y) + fofs);
                float4 v0 = hp[0];
                float4 v1 = hp[1];
                acc[0] = fmaf(ps.x, v0.x, acc[0]);
                acc[1] = fmaf(ps.x, v0.y, acc[1]);
                acc[2] = fmaf(ps.x, v0.z, acc[2]);
                acc[3] = fmaf(ps.x, v0.w, acc[3]);
                acc[4] = fmaf(ps.x, v1.x, acc[4]);
                acc[5] = fmaf(ps.x, v1.y, acc[5]);
                acc[6] = fmaf(ps.x, v1.z, acc[6]);
                acc[7] = fmaf(ps.x, v1.w, acc[7]);
            }
        } else {
            for (int j = 0; j < cnt; j += 4) {
                int eidx = j + g;
                if (eidx < cnt) {
                    float2 ps = buf[hd][eidx];
                    const float4* hp = (const float4*)(g_hf + __float_as_int(ps.y) + fofs);
                    float4 v0 = hp[0];
                    float4 v1 = hp[1];
                    acc[0] = fmaf(ps.x, v0.x, acc[0]);
                    acc[1] = fmaf(ps.x, v0.y, acc[1]);
                    acc[2] = fmaf(ps.x, v0.z, acc[2]);
                    acc[3] = fmaf(ps.x, v0.w, acc[3]);
                    acc[4] = fmaf(ps.x, v1.x, acc[4]);
                    acc[5] = fmaf(ps.x, v1.y, acc[5]);
                    acc[6] = fmaf(ps.x, v1.z, acc[6]);
                    acc[7] = fmaf(ps.x, v1.w, acc[7]);
                }
            }
        }
        __syncwarp();
    }

    #pragma unroll
    for (int o = 16; o > 0; o >>= 1)
        ssum += __shfl_xor_sync(0xFFFFFFFFu, ssum, o);

    // combine the 4 edge-groups (g lives in lane bits 3,4)
    #pragma unroll
    for (int q = 0; q < 8; ++q) {
        acc[q] += __shfl_xor_sync(0xFFFFFFFFu, acc[q], 8);
        acc[q] += __shfl_xor_sync(0xFFFFFFFFu, acc[q], 16);
    }

    float inv = (ssum > 0.f) ? (1.0f / ssum) : 0.f;

    if (g == 0) {   // lanes 0..7 hold the final octet sums
        const float4* bp = (const float4*)(bias + fofs);
        float4 b0 = bp[0], b1 = bp[1];
        float4 o0 = make_float4(acc[0] * inv + b0.x, acc[1] * inv + b0.y,
                                acc[2] * inv + b0.z, acc[3] * inv + b0.w);
        float4 o1 = make_float4(acc[4] * inv + b1.x, acc[5] * inv + b1.y,
                                acc[6] * inv + b1.z, acc[7] * inv + b1.w);
        float4* op = (float4*)(out + n * HF + fofs);
        op[0] = o0;
        op[1] = o1;
    }
}

// ------------------------------- launcher ------------------------------------
extern "C" void kernel_launch(void* const* d_in, const int* in_sizes, int n_in,
                              void* d_out, int out_size)
{
    const float* feat   = (const float*)d_in[0];
    const float* W      = (const float*)d_in[1];
    const float* attn_l = (const float*)d_in[2];
    const float* attn_r = (const float*)d_in[3];
    const float* bias   = (const float*)d_in[4];
    const int*   src    = (const int*)d_in[5];
    const int*   dst    = (const int*)d_in[6];
    float* out = (float*)d_out;

    cudaFuncSetAttribute(gemm_hmma_kernel,
                         cudaFuncAttributeMaxDynamicSharedMemorySize, SM_TOTAL);

    // #1: feat split + edge count + W transpose
    asplit_w_kernel<<<(N_NODES * IN_FEATS / 4 + 255) / 256, 256>>>(feat, W, dst);
    // #2: persistent GEMM + fused el/er (+ CSR scan in block 0)
    gemm_hmma_kernel<<<GRID_GEMM, 256, SM_TOTAL>>>(attn_l, attn_r);
    // #3: CSR fill + CSR-ordered leaky logits (2 threads/edge)
    fill_logits_kernel<<<625, 512>>>(src, dst);
    // #4: softmax + aggregation (+ counter re-zero for next replay)
    aggregate_kernel<<<N_NODES, 256>>>(bias, out);
}

// round 16
// speedup vs baseline: 1.1388x; 1.1388x over previous
#include <cuda_runtime.h>
#include <cuda_fp16.h>
#include <math.h>
#include <stdint.h>

// Problem constants
#define N_NODES   10000
#define N_EDGES   160000
#define IN_FEATS  512
#define HEADS     8
#define OUT_FEATS 64
#define HF        (HEADS * OUT_FEATS)   // 512
#define NEG_SLOPE 0.2f

// ---------------- scratch (device globals; no allocs allowed) ----------------
// NOTE: zero-initialized at load; aggregate_kernel re-zeros the counters it
// consumed so every graph replay sees identical initial state.
__device__ __half g_hh[N_NODES * HF];        // projected features, fp16
__device__ float g_el[N_NODES * HEADS];
__device__ float g_er[N_NODES * HEADS];
__device__ int   g_cnt[N_NODES + 1];
__device__ int   g_off[N_NODES + 1];
__device__ int   g_cur[N_NODES];
__device__ int   g_srcp[N_EDGES];            // src*HF per CSR slot
__device__ float g_e[N_EDGES * HEADS];       // leaky logits per CSR slot
__device__ int   g_tile;
__device__ __half g_W16[HF * IN_FEATS];      // W^T fp16: [n][k]
__device__ __half g_Ah16[N_NODES * IN_FEATS]; // feat fp16 hi: [m][k]
__device__ __half g_Al16[N_NODES * IN_FEATS]; // feat fp16 lo: [m][k]

// ------------------------------ PTX helpers ----------------------------------
__device__ __forceinline__ uint32_t smem_u32(const void* p) {
    uint32_t a;
    asm("{ .reg .u64 t; cvta.to.shared.u64 t, %1; cvt.u32.u64 %0, t; }"
        : "=r"(a) : "l"(p));
    return a;
}
__device__ __forceinline__ void cp_async16(uint32_t sa, const void* gp) {
    asm volatile("cp.async.cg.shared.global [%0], [%1], 16;"
                 :: "r"(sa), "l"(gp));
}
__device__ __forceinline__ void cp_async16z(uint32_t sa, const void* gp, int sz) {
    asm volatile("cp.async.cg.shared.global [%0], [%1], 16, %2;"
                 :: "r"(sa), "l"(gp), "r"(sz));
}
__device__ __forceinline__ void cp_commit() {
    asm volatile("cp.async.commit_group;" ::: "memory");
}
template <int N>
__device__ __forceinline__ void cp_wait() {
    asm volatile("cp.async.wait_group %0;" :: "n"(N) : "memory");
}
__device__ __forceinline__ void ldsm4(uint32_t* r, uint32_t addr) {
    asm volatile("ldmatrix.sync.aligned.m8n8.x4.shared.b16 {%0,%1,%2,%3}, [%4];"
                 : "=r"(r[0]), "=r"(r[1]), "=r"(r[2]), "=r"(r[3]) : "r"(addr));
}
__device__ __forceinline__ void mma16816(float* d, const uint32_t* a, const uint32_t* b) {
    asm volatile(
        "mma.sync.aligned.m16n8k16.row.col.f32.f16.f16.f32 "
        "{%0,%1,%2,%3}, {%4,%5,%6,%7}, {%8,%9}, {%0,%1,%2,%3};"
        : "+f"(d[0]), "+f"(d[1]), "+f"(d[2]), "+f"(d[3])
        : "r"(a[0]), "r"(a[1]), "r"(a[2]), "r"(a[3]), "r"(b[0]), "r"(b[1]));
}

// ===== pre-pass: feat fp16 hi/lo split + CSR edge count + W transpose =========
__global__ __launch_bounds__(256) void asplit_w_kernel(
    const float* __restrict__ feat, const float* __restrict__ W,
    const int* __restrict__ dst)
{
    int tid = threadIdx.x;

    // fused edge counting on the first 625 blocks
    int eid = blockIdx.x * 256 + tid;
    if (eid < N_EDGES) atomicAdd(&g_cnt[dst[eid]], 1);

    // W transpose on blocks 0..255
    __shared__ float tile[32][33];
    if (blockIdx.x < 256) {
        int bx = blockIdx.x & 15;   // n tile
        int by = blockIdx.x >> 4;   // k tile
        int tx = tid & 31;
        int ty = tid >> 5;
        for (int i = ty; i < 32; i += 8)
            tile[i][tx] = W[(by * 32 + i) * HF + bx * 32 + tx];
        __syncthreads();
        int k = by * 32 + tx;
        for (int i = ty; i < 32; i += 8) {
            int n = bx * 32 + i;
            g_W16[n * IN_FEATS + k] = __float2half_rn(tile[tx][i]);
        }
    }

    // feat split: one float4 per thread
    int i = blockIdx.x * 256 + tid;
    if (i >= N_NODES * IN_FEATS / 4) return;
    float4 v = ((const float4*)feat)[i];
    float f[4] = {v.x, v.y, v.z, v.w};
    __half h[4], lo[4];
    #pragma unroll
    for (int j = 0; j < 4; ++j) {
        h[j]  = __float2half_rn(f[j]);
        lo[j] = __float2half_rn(f[j] - __half2float(h[j]));
    }
    ((uint2*)g_Ah16)[i] = make_uint2(
        ((uint32_t)__half_as_ushort(h[1]) << 16) | __half_as_ushort(h[0]),
        ((uint32_t)__half_as_ushort(h[3]) << 16) | __half_as_ushort(h[2]));
    ((uint2*)g_Al16)[i] = make_uint2(
        ((uint32_t)__half_as_ushort(lo[1]) << 16) | __half_as_ushort(lo[0]),
        ((uint32_t)__half_as_ushort(lo[3]) << 16) | __half_as_ushort(lo[2]));
}

// ============== persistent HMMA fp16x2 GEMM + fused el/er + scan ==============
#define BM 64
#define BN 128
#define BK 32
#define NCH (IN_FEATS / BK)        // 16
#define ROWB 80                    // 64B data + 16B pad
#define AH_OFF 0
#define AL_OFF (BM * ROWB)               // 5120
#define B_OFF  (2 * BM * ROWB)           // 10240
#define STAGE_BYTES (B_OFF + BN * ROWB)  // 20480
#define SM_TOTAL (3 * STAGE_BYTES)       // 61440
#define MT_TILES 157
#define NT_TILES 4
#define NTILES (MT_TILES * NT_TILES)     // 628
#define GRID_GEMM 444
#define SCAN_CHUNK 40                    // 256 threads x 40 >= 10001

__global__ __launch_bounds__(256, 3) void gemm_hmma_kernel(
    const float* __restrict__ attn_l,
    const float* __restrict__ attn_r)
{
    extern __shared__ char smem[];
    __shared__ int sh_tile;
    uint32_t sb = smem_u32(smem);
    int tid = threadIdx.x;
    int w = tid >> 5;
    int l = tid & 31;
    int wm = (w >> 2) * 32;
    int wn = (w & 3) * 32;
    int lr = l & 15;
    int kc = (l & 16) ? 8 : 0;

    // ---- block 0: CSR exclusive scan (two-pass, L2-resident g_cnt) ----
    if (blockIdx.x == 0) {
        int* ssum = (int*)smem;
        int base = tid * SCAN_CHUNK;
        int s = 0;
        for (int j = 0; j < SCAN_CHUNK; ++j) {
            int idx = base + j;
            if (idx < N_NODES) s += g_cnt[idx];
        }
        ssum[tid] = s;
        __syncthreads();
        for (int d = 1; d < 256; d <<= 1) {
            int add = (tid >= d) ? ssum[tid - d] : 0;
            __syncthreads();
            ssum[tid] += add;
            __syncthreads();
        }
        int run = ssum[tid] - s;
        for (int j = 0; j < SCAN_CHUNK; ++j) {
            int idx = base + j;
            if (idx <= N_NODES) {
                g_off[idx] = run;
                if (idx < N_NODES) run += g_cnt[idx];
            }
        }
        __syncthreads();
    }

    uint32_t aoff0 = (uint32_t)(wm + lr) * ROWB;
    uint32_t aoff1 = (uint32_t)(wm + 16 + lr) * ROWB;
    uint32_t boff0 = (uint32_t)(wn + lr) * ROWB;
    uint32_t boff1 = (uint32_t)(wn + 16 + lr) * ROWB;
    int arow = tid >> 2;
    int ac16 = tid & 3;
    int brow0 = tid >> 1;
    int bseg = (tid & 1) * 2;

    for (;;) {
        if (tid == 0) sh_tile = atomicAdd(&g_tile, 1);
        __syncthreads();
        int t = sh_tile;
        if (t >= NTILES) break;
        int bm = (t >> 2) * BM;
        int bn = (t & 3) * BN;

        float acc[2][4][4];
        #pragma unroll
        for (int a = 0; a < 2; ++a)
            #pragma unroll
            for (int b = 0; b < 4; ++b)
                #pragma unroll
                for (int c = 0; c < 4; ++c) acc[a][b][c] = 0.f;

        int agrow = bm + arow;
        int asz = (agrow < N_NODES) ? 16 : 0;
        if (agrow >= N_NODES) agrow = 0;
        const __half* apH = g_Ah16 + (size_t)agrow * IN_FEATS + ac16 * 8;
        const __half* apL = g_Al16 + (size_t)agrow * IN_FEATS + ac16 * 8;
        const __half* bp0 = g_W16 + (size_t)(bn + brow0) * IN_FEATS + bseg * 8;
        uint32_t sA = (uint32_t)arow * ROWB + ac16 * 16;
        uint32_t sB = (uint32_t)brow0 * ROWB + bseg * 16;

        auto load_chunk = [&](int c) {
            int k0 = c * BK;
            uint32_t st = sb + (c % 3) * STAGE_BYTES;
            cp_async16z(st + AH_OFF + sA, apH + k0, asz);
            cp_async16z(st + AL_OFF + sA, apL + k0, asz);
            cp_async16(st + B_OFF + sB,      bp0 + k0);
            cp_async16(st + B_OFF + sB + 16, bp0 + k0 + 8);
            cp_commit();
        };

        load_chunk(0);
        load_chunk(1);

        for (int c = 0; c < NCH; ++c) {
            if (c < NCH - 1) cp_wait<1>(); else cp_wait<0>();
            __syncthreads();
            if (c + 2 < NCH) load_chunk(c + 2);

            uint32_t st = sb + (c % 3) * STAGE_BYTES;
            uint32_t sA_h = st + AH_OFF;
            uint32_t sA_l = st + AL_OFF;
            uint32_t sB_h = st + B_OFF;

            #pragma unroll
            for (int ks = 0; ks < 2; ++ks) {
                uint32_t koff = (ks * 16 + kc) * 2;
                uint32_t bf[4][2];
                {
                    uint32_t r[4];
                    ldsm4(r, sB_h + boff0 + koff);
                    bf[0][0] = r[0]; bf[1][0] = r[1];
                    bf[0][1] = r[2]; bf[1][1] = r[3];
                    ldsm4(r, sB_h + boff1 + koff);
                    bf[2][0] = r[0]; bf[3][0] = r[1];
                    bf[2][1] = r[2]; bf[3][1] = r[3];
                }
                uint32_t ahf[2][4], alf[2][4];
                ldsm4(ahf[0], sA_h + aoff0 + koff);
                ldsm4(ahf[1], sA_h + aoff1 + koff);
                ldsm4(alf[0], sA_l + aoff0 + koff);
                ldsm4(alf[1], sA_l + aoff1 + koff);
                #pragma unroll
                for (int fm = 0; fm < 2; ++fm)
                    #pragma unroll
                    for (int fn = 0; fn < 4; ++fn)
                        mma16816(acc[fm][fn], ahf[fm], bf[fn]);
                #pragma unroll
                for (int fm = 0; fm < 2; ++fm)
                    #pragma unroll
                    for (int fn = 0; fn < 4; ++fn)
                        mma16816(acc[fm][fn], alf[fm], bf[fn]);
            }
        }

        // ---- epilogue 1: h stores (fp16) ----
        #pragma unroll
        for (int fm = 0; fm < 2; ++fm) {
            int r0 = bm + wm + fm * 16 + (l >> 2);
            int r1 = r0 + 8;
            #pragma unroll
            for (int fn = 0; fn < 4; ++fn) {
                int col = bn + wn + fn * 8 + (l & 3) * 2;
                if (r0 < N_NODES)
                    *(__half2*)(g_hh + (size_t)r0 * HF + col) =
                        __floats2half2_rn(acc[fm][fn][0], acc[fm][fn][1]);
                if (r1 < N_NODES)
                    *(__half2*)(g_hh + (size_t)r1 * HF + col) =
                        __floats2half2_rn(acc[fm][fn][2], acc[fm][fn][3]);
            }
        }

        // ---- epilogue 2: fused el/er (deterministic) ----
        float* pel = (float*)smem;
        float* per = (float*)smem + BM * 4;
        float avl[8], avr[8];
        #pragma unroll
        for (int fn = 0; fn < 4; ++fn) {
            int colg = bn + wn + fn * 8 + (l & 3) * 2;
            avl[2*fn]   = attn_l[colg];
            avl[2*fn+1] = attn_l[colg + 1];
            avr[2*fn]   = attn_r[colg];
            avr[2*fn+1] = attn_r[colg + 1];
        }
        int wnidx = w & 3;
        __syncthreads();
        #pragma unroll
        for (int fm = 0; fm < 2; ++fm) {
            float pl0 = 0.f, pl1 = 0.f, pr0 = 0.f, pr1 = 0.f;
            #pragma unroll
            for (int fn = 0; fn < 4; ++fn) {
                pl0 += acc[fm][fn][0] * avl[2*fn] + acc[fm][fn][1] * avl[2*fn+1];
                pl1 += acc[fm][fn][2] * avl[2*fn] + acc[fm][fn][3] * avl[2*fn+1];
                pr0 += acc[fm][fn][0] * avr[2*fn] + acc[fm][fn][1] * avr[2*fn+1];
                pr1 += acc[fm][fn][2] * avr[2*fn] + acc[fm][fn][3] * avr[2*fn+1];
            }
            #pragma unroll
            for (int o = 1; o <= 2; o <<= 1) {
                pl0 += __shfl_xor_sync(0xFFFFFFFFu, pl0, o);
                pl1 += __shfl_xor_sync(0xFFFFFFFFu, pl1, o);
                pr0 += __shfl_xor_sync(0xFFFFFFFFu, pr0, o);
                pr1 += __shfl_xor_sync(0xFFFFFFFFu, pr1, o);
            }
            if ((l & 3) == 0) {
                int lr0 = wm + fm * 16 + (l >> 2);
                int lr1 = lr0 + 8;
                pel[lr0 * 4 + wnidx] = pl0;
                pel[lr1 * 4 + wnidx] = pl1;
                per[lr0 * 4 + wnidx] = pr0;
                per[lr1 * 4 + wnidx] = pr1;
            }
        }
        __syncthreads();
        if (tid < 2 * BM) {
            int row = tid >> 1;
            int tt = tid & 1;
            int grow = bm + row;
            if (grow < N_NODES) {
                float el = pel[row * 4 + 2 * tt] + pel[row * 4 + 2 * tt + 1];
                float er = per[row * 4 + 2 * tt] + per[row * 4 + 2 * tt + 1];
                int hd = (t & 3) * 2 + tt;
                g_el[grow * HEADS + hd] = el;
                g_er[grow * HEADS + hd] = er;
            }
        }
        __syncthreads();
    }
}

// -------- fill CSR slots + CSR-ordered leaky logits, 2 threads/edge ----------
__global__ __launch_bounds__(512) void fill_logits_kernel(
    const int* __restrict__ src, const int* __restrict__ dst)
{
    int tid = threadIdx.x;
    int e = blockIdx.x * 256 + (tid >> 1);      // exactly covers 160000
    int half = tid & 1;
    int lane = tid & 31;

    int d = dst[e];
    int s = src[e];
    int slot = 0;
    if (half == 0) slot = atomicAdd(&g_cur[d], 1);
    slot = __shfl_sync(0xFFFFFFFFu, slot, lane & ~1);
    int i = g_off[d] + slot;
    if (half == 0) g_srcp[i] = s * HF;          // pre-scaled row offset

    float4 lv = *(const float4*)&g_el[s * HEADS + half * 4];
    float4 rv = *(const float4*)&g_er[d * HEADS + half * 4];
    float v0 = lv.x + rv.x, v1 = lv.y + rv.y, v2 = lv.z + rv.z, v3 = lv.w + rv.w;
    v0 = (v0 > 0.f) ? v0 : NEG_SLOPE * v0;
    v1 = (v1 > 0.f) ? v1 : NEG_SLOPE * v1;
    v2 = (v2 > 0.f) ? v2 : NEG_SLOPE * v2;
    v3 = (v3 > 0.f) ? v3 : NEG_SLOPE * v3;
    *(float4*)&g_e[i * HEADS + half * 4] = make_float4(v0, v1, v2, v3);
}

// ---------- softmax (no max shift; logits bounded) + aggregation -------------
// One block/node, one warp/head. Logit chunk staged cooperatively in SMEM
// (coalesced, conflict-free stride-9 columns); gather via fp16 LDG.128,
// 4 edges per warp-iteration.
__global__ __launch_bounds__(256) void aggregate_kernel(
    const float* __restrict__ bias,
    float* __restrict__ out)
{
    __shared__ float se[32 * 9];    // chunk logits, se[j*9+hd], pad -> no conflicts
    __shared__ int   ssrc[32];
    __shared__ float2 buf[8][32];   // (p, srcHF-as-float) per warp
    int n = blockIdx.x;

    if (threadIdx.x == 0) {
        g_cur[n] = 0;
        g_cnt[n] = 0;
        if (n == 0) { g_cnt[N_NODES] = 0; g_tile = 0; }
    }

    int hd = threadIdx.x >> 5;
    int lane = threadIdx.x & 31;
    int g = lane >> 3;          // 0..3 (edge in quad)
    int fl = lane & 7;          // 0..7 (feature octet)
    int fofs = hd * OUT_FEATS + fl * 8;

    int beg = g_off[n];
    int end = g_off[n + 1];

    float ssum = 0.f;
    float acc[8];
    #pragma unroll
    for (int q = 0; q < 8; ++q) acc[q] = 0.f;

    for (int base = beg; base < end; base += 32) {
        int cnt = end - base; if (cnt > 32) cnt = 32;
        __syncthreads();   // previous chunk's se/ssrc reads done
        // cooperative coalesced load of cnt*8 logits + cnt src offsets
        for (int k = threadIdx.x; k < cnt * 8; k += 256)
            se[(k >> 3) * 9 + (k & 7)] = g_e[base * 8 + k];
        if (threadIdx.x < cnt)
            ssrc[threadIdx.x] = g_srcp[base + threadIdx.x];
        __syncthreads();

        if (lane < cnt) {
            float p = __expf(se[lane * 9 + hd]);   // no shift: |e| <~ 10
            ssum += p;
            buf[hd][lane] = make_float2(p, __int_as_float(ssrc[lane]));
        }
        __syncwarp();
        for (int j = 0; j < cnt; j += 4) {
            int eidx = j + g;
            if (eidx < cnt) {
                float2 ps = buf[hd][eidx];
                uint4 v = *(const uint4*)(g_hh + __float_as_int(ps.y) + fofs);
                const __half2* h2 = (const __half2*)&v;
                #pragma unroll
                for (int q = 0; q < 4; ++q) {
                    float2 f = __half22float2(h2[q]);
                    acc[2*q]   = fmaf(ps.x, f.x, acc[2*q]);
                    acc[2*q+1] = fmaf(ps.x, f.y, acc[2*q+1]);
                }
            }
        }
        __syncwarp();   // buf reads done before next chunk overwrites
    }

    #pragma unroll
    for (int o = 16; o > 0; o >>= 1)
        ssum += __shfl_xor_sync(0xFFFFFFFFu, ssum, o);

    // combine the 4 edge-groups (g lives in lane bits 3,4)
    #pragma unroll
    for (int q = 0; q < 8; ++q) {
        acc[q] += __shfl_xor_sync(0xFFFFFFFFu, acc[q], 8);
        acc[q] += __shfl_xor_sync(0xFFFFFFFFu, acc[q], 16);
    }

    float inv = (ssum > 0.f) ? (1.0f / ssum) : 0.f;

    if (g == 0) {   // lanes 0..7 hold the final octet sums
        const float4* bp = (const float4*)(bias + fofs);
        float4 b0 = bp[0], b1 = bp[1];
        float4 o0 = make_float4(acc[0] * inv + b0.x, acc[1] * inv + b0.y,
                                acc[2] * inv + b0.z, acc[3] * inv + b0.w);
        float4 o1 = make_float4(acc[4] * inv + b1.x, acc[5] * inv + b1.y,
                                acc[6] * inv + b1.z, acc[7] * inv + b1.w);
        float4* op = (float4*)(out + n * HF + fofs);
        op[0] = o0;
        op[1] = o1;
    }
}

// ------------------------------- launcher ------------------------------------
extern "C" void kernel_launch(void* const* d_in, const int* in_sizes, int n_in,
                              void* d_out, int out_size)
{
    const float* feat   = (const float*)d_in[0];
    const float* W      = (const float*)d_in[1];
    const float* attn_l = (const float*)d_in[2];
    const float* attn_r = (const float*)d_in[3];
    const float* bias   = (const float*)d_in[4];
    const int*   src    = (const int*)d_in[5];
    const int*   dst    = (const int*)d_in[6];
    float* out = (float*)d_out;

    cudaFuncSetAttribute(gemm_hmma_kernel,
                         cudaFuncAttributeMaxDynamicSharedMemorySize, SM_TOTAL);

    // #1: feat split + edge count + W transpose
    asplit_w_kernel<<<(N_NODES * IN_FEATS / 4 + 255) / 256, 256>>>(feat, W, dst);
    // #2: persistent GEMM + fused el/er (+ CSR scan in block 0)
    gemm_hmma_kernel<<<GRID_GEMM, 256, SM_TOTAL>>>(attn_l, attn_r);
    // #3: CSR fill + CSR-ordered leaky logits (2 threads/edge)
    fill_logits_kernel<<<625, 512>>>(src, dst);
    // #4: softmax + aggregation (+ counter re-zero for next replay)
    aggregate_kernel<<<N_NODES, 256>>>(bias, out);
}

// round 17
// speedup vs baseline: 1.4194x; 1.2464x over previous
#include <cuda_runtime.h>
#include <cuda_fp16.h>
#include <math.h>
#include <stdint.h>

// Problem constants
#define N_NODES   10000
#define N_EDGES   160000
#define IN_FEATS  512
#define HEADS     8
#define OUT_FEATS 64
#define HF        (HEADS * OUT_FEATS)   // 512
#define NEG_SLOPE 0.2f

// ---------------- scratch (device globals; no allocs allowed) ----------------
// NOTE: zero-initialized at load; aggregate_kernel re-zeros the counters it
// consumed so every graph replay sees identical initial state.
__device__ __half g_hh[N_NODES * HF];        // projected features, fp16
__device__ float g_el[N_NODES * HEADS];
__device__ float g_er[N_NODES * HEADS];
__device__ int   g_cnt[N_NODES + 1];
__device__ int   g_off[N_NODES + 1];
__device__ int   g_cur[N_NODES];
__device__ int   g_srcp[N_EDGES];            // src*HF per CSR slot
__device__ float g_e[N_EDGES * HEADS];       // leaky logits per CSR slot
__device__ int   g_tile;
__device__ __half g_W16[HF * IN_FEATS];      // W^T fp16: [n][k]
__device__ __half g_A16[N_NODES * IN_FEATS]; // feat fp16: [m][k]

// ------------------------------ PTX helpers ----------------------------------
__device__ __forceinline__ uint32_t smem_u32(const void* p) {
    uint32_t a;
    asm("{ .reg .u64 t; cvta.to.shared.u64 t, %1; cvt.u32.u64 %0, t; }"
        : "=r"(a) : "l"(p));
    return a;
}
__device__ __forceinline__ void cp_async16(uint32_t sa, const void* gp) {
    asm volatile("cp.async.cg.shared.global [%0], [%1], 16;"
                 :: "r"(sa), "l"(gp));
}
__device__ __forceinline__ void cp_async16z(uint32_t sa, const void* gp, int sz) {
    asm volatile("cp.async.cg.shared.global [%0], [%1], 16, %2;"
                 :: "r"(sa), "l"(gp), "r"(sz));
}
__device__ __forceinline__ void cp_commit() {
    asm volatile("cp.async.commit_group;" ::: "memory");
}
template <int N>
__device__ __forceinline__ void cp_wait() {
    asm volatile("cp.async.wait_group %0;" :: "n"(N) : "memory");
}
__device__ __forceinline__ void ldsm4(uint32_t* r, uint32_t addr) {
    asm volatile("ldmatrix.sync.aligned.m8n8.x4.shared.b16 {%0,%1,%2,%3}, [%4];"
                 : "=r"(r[0]), "=r"(r[1]), "=r"(r[2]), "=r"(r[3]) : "r"(addr));
}
__device__ __forceinline__ void mma16816(float* d, const uint32_t* a, const uint32_t* b) {
    asm volatile(
        "mma.sync.aligned.m16n8k16.row.col.f32.f16.f16.f32 "
        "{%0,%1,%2,%3}, {%4,%5,%6,%7}, {%8,%9}, {%0,%1,%2,%3};"
        : "+f"(d[0]), "+f"(d[1]), "+f"(d[2]), "+f"(d[3])
        : "r"(a[0]), "r"(a[1]), "r"(a[2]), "r"(a[3]), "r"(b[0]), "r"(b[1]));
}

// ===== pre-pass: feat fp16 convert + CSR edge count + W transpose =============
__global__ __launch_bounds__(256) void asplit_w_kernel(
    const float* __restrict__ feat, const float* __restrict__ W,
    const int* __restrict__ dst)
{
    int tid = threadIdx.x;

    // fused edge counting on the first 625 blocks
    int eid = blockIdx.x * 256 + tid;
    if (eid < N_EDGES) atomicAdd(&g_cnt[dst[eid]], 1);

    // W transpose on blocks 0..255
    __shared__ float tile[32][33];
    if (blockIdx.x < 256) {
        int bx = blockIdx.x & 15;   // n tile
        int by = blockIdx.x >> 4;   // k tile
        int tx = tid & 31;
        int ty = tid >> 5;
        for (int i = ty; i < 32; i += 8)
            tile[i][tx] = W[(by * 32 + i) * HF + bx * 32 + tx];
        __syncthreads();
        int k = by * 32 + tx;
        for (int i = ty; i < 32; i += 8) {
            int n = bx * 32 + i;
            g_W16[n * IN_FEATS + k] = __float2half_rn(tile[tx][i]);
        }
    }

    // feat convert: one float4 per thread
    int i = blockIdx.x * 256 + tid;
    if (i >= N_NODES * IN_FEATS / 4) return;
    float4 v = ((const float4*)feat)[i];
    __half h0 = __float2half_rn(v.x);
    __half h1 = __float2half_rn(v.y);
    __half h2 = __float2half_rn(v.z);
    __half h3 = __float2half_rn(v.w);
    ((uint2*)g_A16)[i] = make_uint2(
        ((uint32_t)__half_as_ushort(h1) << 16) | __half_as_ushort(h0),
        ((uint32_t)__half_as_ushort(h3) << 16) | __half_as_ushort(h2));
}

// ============== persistent HMMA fp16 GEMM + fused el/er + scan ================
#define BM 64
#define BN 128
#define BK 32
#define NCH (IN_FEATS / BK)        // 16
#define ROWB 80                    // 64B data + 16B pad
#define A_OFF 0
#define B_OFF  (BM * ROWB)               // 5120
#define STAGE_BYTES (B_OFF + BN * ROWB)  // 15360
#define SM_TOTAL (3 * STAGE_BYTES)       // 46080
#define MT_TILES 157
#define NT_TILES 4
#define NTILES (MT_TILES * NT_TILES)     // 628
#define GRID_GEMM 444
#define SCAN_CHUNK 40                    // 256 threads x 40 >= 10001

__global__ __launch_bounds__(256, 3) void gemm_hmma_kernel(
    const float* __restrict__ attn_l,
    const float* __restrict__ attn_r)
{
    extern __shared__ char smem[];
    __shared__ int sh_tile;
    uint32_t sb = smem_u32(smem);
    int tid = threadIdx.x;
    int w = tid >> 5;
    int l = tid & 31;
    int wm = (w >> 2) * 32;
    int wn = (w & 3) * 32;
    int lr = l & 15;
    int kc = (l & 16) ? 8 : 0;

    // ---- block 0: CSR exclusive scan (two-pass, L2-resident g_cnt) ----
    if (blockIdx.x == 0) {
        int* ssum = (int*)smem;
        int base = tid * SCAN_CHUNK;
        int s = 0;
        for (int j = 0; j < SCAN_CHUNK; ++j) {
            int idx = base + j;
            if (idx < N_NODES) s += g_cnt[idx];
        }
        ssum[tid] = s;
        __syncthreads();
        for (int d = 1; d < 256; d <<= 1) {
            int add = (tid >= d) ? ssum[tid - d] : 0;
            __syncthreads();
            ssum[tid] += add;
            __syncthreads();
        }
        int run = ssum[tid] - s;
        for (int j = 0; j < SCAN_CHUNK; ++j) {
            int idx = base + j;
            if (idx <= N_NODES) {
                g_off[idx] = run;
                if (idx < N_NODES) run += g_cnt[idx];
            }
        }
        __syncthreads();
    }

    uint32_t aoff0 = (uint32_t)(wm + lr) * ROWB;
    uint32_t aoff1 = (uint32_t)(wm + 16 + lr) * ROWB;
    uint32_t boff0 = (uint32_t)(wn + lr) * ROWB;
    uint32_t boff1 = (uint32_t)(wn + 16 + lr) * ROWB;
    int arow = tid >> 2;
    int ac16 = tid & 3;
    int brow0 = tid >> 1;
    int bseg = (tid & 1) * 2;

    for (;;) {
        if (tid == 0) sh_tile = atomicAdd(&g_tile, 1);
        __syncthreads();
        int t = sh_tile;
        if (t >= NTILES) break;
        int bm = (t >> 2) * BM;
        int bn = (t & 3) * BN;

        float acc[2][4][4];
        #pragma unroll
        for (int a = 0; a < 2; ++a)
            #pragma unroll
            for (int b = 0; b < 4; ++b)
                #pragma unroll
                for (int c = 0; c < 4; ++c) acc[a][b][c] = 0.f;

        int agrow = bm + arow;
        int asz = (agrow < N_NODES) ? 16 : 0;
        if (agrow >= N_NODES) agrow = 0;
        const __half* apA = g_A16 + (size_t)agrow * IN_FEATS + ac16 * 8;
        const __half* bp0 = g_W16 + (size_t)(bn + brow0) * IN_FEATS + bseg * 8;
        uint32_t sA = (uint32_t)arow * ROWB + ac16 * 16;
        uint32_t sB = (uint32_t)brow0 * ROWB + bseg * 16;

        auto load_chunk = [&](int c) {
            int k0 = c * BK;
            uint32_t st = sb + (c % 3) * STAGE_BYTES;
            cp_async16z(st + A_OFF + sA, apA + k0, asz);
            cp_async16(st + B_OFF + sB,      bp0 + k0);
            cp_async16(st + B_OFF + sB + 16, bp0 + k0 + 8);
            cp_commit();
        };

        load_chunk(0);
        load_chunk(1);

        for (int c = 0; c < NCH; ++c) {
            if (c < NCH - 1) cp_wait<1>(); else cp_wait<0>();
            __syncthreads();
            if (c + 2 < NCH) load_chunk(c + 2);

            uint32_t st = sb + (c % 3) * STAGE_BYTES;
            uint32_t sA_h = st + A_OFF;
            uint32_t sB_h = st + B_OFF;

            #pragma unroll
            for (int ks = 0; ks < 2; ++ks) {
                uint32_t koff = (ks * 16 + kc) * 2;
                uint32_t bf[4][2];
                {
                    uint32_t r[4];
                    ldsm4(r, sB_h + boff0 + koff);
                    bf[0][0] = r[0]; bf[1][0] = r[1];
                    bf[0][1] = r[2]; bf[1][1] = r[3];
                    ldsm4(r, sB_h + boff1 + koff);
                    bf[2][0] = r[0]; bf[3][0] = r[1];
                    bf[2][1] = r[2]; bf[3][1] = r[3];
                }
                uint32_t ahf[2][4];
                ldsm4(ahf[0], sA_h + aoff0 + koff);
                ldsm4(ahf[1], sA_h + aoff1 + koff);
                #pragma unroll
                for (int fm = 0; fm < 2; ++fm)
                    #pragma unroll
                    for (int fn = 0; fn < 4; ++fn)
                        mma16816(acc[fm][fn], ahf[fm], bf[fn]);
            }
        }

        // ---- epilogue 1: h stores (fp16) ----
        #pragma unroll
        for (int fm = 0; fm < 2; ++fm) {
            int r0 = bm + wm + fm * 16 + (l >> 2);
            int r1 = r0 + 8;
            #pragma unroll
            for (int fn = 0; fn < 4; ++fn) {
                int col = bn + wn + fn * 8 + (l & 3) * 2;
                if (r0 < N_NODES)
                    *(__half2*)(g_hh + (size_t)r0 * HF + col) =
                        __floats2half2_rn(acc[fm][fn][0], acc[fm][fn][1]);
                if (r1 < N_NODES)
                    *(__half2*)(g_hh + (size_t)r1 * HF + col) =
                        __floats2half2_rn(acc[fm][fn][2], acc[fm][fn][3]);
            }
        }

        // ---- epilogue 2: fused el/er (deterministic) ----
        float* pel = (float*)smem;
        float* per = (float*)smem + BM * 4;
        float avl[8], avr[8];
        #pragma unroll
        for (int fn = 0; fn < 4; ++fn) {
            int colg = bn + wn + fn * 8 + (l & 3) * 2;
            avl[2*fn]   = attn_l[colg];
            avl[2*fn+1] = attn_l[colg + 1];
            avr[2*fn]   = attn_r[colg];
            avr[2*fn+1] = attn_r[colg + 1];
        }
        int wnidx = w & 3;
        __syncthreads();
        #pragma unroll
        for (int fm = 0; fm < 2; ++fm) {
            float pl0 = 0.f, pl1 = 0.f, pr0 = 0.f, pr1 = 0.f;
            #pragma unroll
            for (int fn = 0; fn < 4; ++fn) {
                pl0 += acc[fm][fn][0] * avl[2*fn] + acc[fm][fn][1] * avl[2*fn+1];
                pl1 += acc[fm][fn][2] * avl[2*fn] + acc[fm][fn][3] * avl[2*fn+1];
                pr0 += acc[fm][fn][0] * avr[2*fn] + acc[fm][fn][1] * avr[2*fn+1];
                pr1 += acc[fm][fn][2] * avr[2*fn] + acc[fm][fn][3] * avr[2*fn+1];
            }
            #pragma unroll
            for (int o = 1; o <= 2; o <<= 1) {
                pl0 += __shfl_xor_sync(0xFFFFFFFFu, pl0, o);
                pl1 += __shfl_xor_sync(0xFFFFFFFFu, pl1, o);
                pr0 += __shfl_xor_sync(0xFFFFFFFFu, pr0, o);
                pr1 += __shfl_xor_sync(0xFFFFFFFFu, pr1, o);
            }
            if ((l & 3) == 0) {
                int lr0 = wm + fm * 16 + (l >> 2);
                int lr1 = lr0 + 8;
                pel[lr0 * 4 + wnidx] = pl0;
                pel[lr1 * 4 + wnidx] = pl1;
                per[lr0 * 4 + wnidx] = pr0;
                per[lr1 * 4 + wnidx] = pr1;
            }
        }
        __syncthreads();
        if (tid < 2 * BM) {
            int row = tid >> 1;
            int tt = tid & 1;
            int grow = bm + row;
            if (grow < N_NODES) {
                float el = pel[row * 4 + 2 * tt] + pel[row * 4 + 2 * tt + 1];
                float er = per[row * 4 + 2 * tt] + per[row * 4 + 2 * tt + 1];
                int hd = (t & 3) * 2 + tt;
                g_el[grow * HEADS + hd] = el;
                g_er[grow * HEADS + hd] = er;
            }
        }
        __syncthreads();
    }
}

// -------- fill CSR slots + CSR-ordered leaky logits, 2 threads/edge ----------
__global__ __launch_bounds__(512) void fill_logits_kernel(
    const int* __restrict__ src, const int* __restrict__ dst)
{
    int tid = threadIdx.x;
    int e = blockIdx.x * 256 + (tid >> 1);      // exactly covers 160000
    int half = tid & 1;
    int lane = tid & 31;

    int d = dst[e];
    int s = src[e];
    int slot = 0;
    if (half == 0) slot = atomicAdd(&g_cur[d], 1);
    slot = __shfl_sync(0xFFFFFFFFu, slot, lane & ~1);
    int i = g_off[d] + slot;
    if (half == 0) g_srcp[i] = s * HF;          // pre-scaled row offset

    float4 lv = *(const float4*)&g_el[s * HEADS + half * 4];
    float4 rv = *(const float4*)&g_er[d * HEADS + half * 4];
    float v0 = lv.x + rv.x, v1 = lv.y + rv.y, v2 = lv.z + rv.z, v3 = lv.w + rv.w;
    v0 = (v0 > 0.f) ? v0 : NEG_SLOPE * v0;
    v1 = (v1 > 0.f) ? v1 : NEG_SLOPE * v1;
    v2 = (v2 > 0.f) ? v2 : NEG_SLOPE * v2;
    v3 = (v3 > 0.f) ? v3 : NEG_SLOPE * v3;
    *(float4*)&g_e[i * HEADS + half * 4] = make_float4(v0, v1, v2, v3);
}

// ---------- softmax (no max shift; logits bounded) + aggregation -------------
// One block/node, one warp/head. 4 edges per warp-iteration via LDG.128:
// g = lane>>3 picks edge in quad, fl = lane&7 picks 8-feature octet.
__global__ __launch_bounds__(256) void aggregate_kernel(
    const float* __restrict__ bias,
    float* __restrict__ out)
{
    __shared__ float2 buf[8][32];   // (p, srcHF-as-float) per warp
    int n = blockIdx.x;

    if (threadIdx.x == 0) {
        g_cur[n] = 0;
        g_cnt[n] = 0;
        if (n == 0) { g_cnt[N_NODES] = 0; g_tile = 0; }
    }

    int hd = threadIdx.x >> 5;
    int lane = threadIdx.x & 31;
    int g = lane >> 3;          // 0..3 (edge in quad)
    int fl = lane & 7;          // 0..7 (feature octet)
    int fofs = hd * OUT_FEATS + fl * 8;

    int beg = g_off[n];
    int end = g_off[n + 1];

    float ssum = 0.f;
    float acc[8];
    #pragma unroll
    for (int q = 0; q < 8; ++q) acc[q] = 0.f;

    for (int base = beg; base < end; base += 32) {
        int cnt = end - base; if (cnt > 32) cnt = 32;
        if (lane < cnt) {
            int i = base + lane;
            float p = __expf(g_e[i * HEADS + hd]);   // no shift: |e| <~ 10
            ssum += p;
            buf[hd][lane] = make_float2(p, __int_as_float(g_srcp[i]));
        }
        __syncwarp();
        for (int j = 0; j < cnt; j += 4) {
            int eidx = j + g;
            if (eidx < cnt) {
                float2 ps = buf[hd][eidx];
                uint4 v = *(const uint4*)(g_hh + __float_as_int(ps.y) + fofs);
                const __half2* h2 = (const __half2*)&v;
                #pragma unroll
                for (int q = 0; q < 4; ++q) {
                    float2 f = __half22float2(h2[q]);
                    acc[2*q]   = fmaf(ps.x, f.x, acc[2*q]);
                    acc[2*q+1] = fmaf(ps.x, f.y, acc[2*q+1]);
                }
            }
        }
        __syncwarp();
    }

    #pragma unroll
    for (int o = 16; o > 0; o >>= 1)
        ssum += __shfl_xor_sync(0xFFFFFFFFu, ssum, o);

    // combine the 4 edge-groups (g lives in lane bits 3,4)
    #pragma unroll
    for (int q = 0; q < 8; ++q) {
        acc[q] += __shfl_xor_sync(0xFFFFFFFFu, acc[q], 8);
        acc[q] += __shfl_xor_sync(0xFFFFFFFFu, acc[q], 16);
    }

    float inv = (ssum > 0.f) ? (1.0f / ssum) : 0.f;

    if (g == 0) {   // lanes 0..7 hold the final octet sums
        const float4* bp = (const float4*)(bias + fofs);
        float4 b0 = bp[0], b1 = bp[1];
        float4 o0 = make_float4(acc[0] * inv + b0.x, acc[1] * inv + b0.y,
                                acc[2] * inv + b0.z, acc[3] * inv + b0.w);
        float4 o1 = make_float4(acc[4] * inv + b1.x, acc[5] * inv + b1.y,
                                acc[6] * inv + b1.z, acc[7] * inv + b1.w);
        float4* op = (float4*)(out + n * HF + fofs);
        op[0] = o0;
        op[1] = o1;
    }
}

// ------------------------------- launcher ------------------------------------
extern "C" void kernel_launch(void* const* d_in, const int* in_sizes, int n_in,
                              void* d_out, int out_size)
{
    const float* feat   = (const float*)d_in[0];
    const float* W      = (const float*)d_in[1];
    const float* attn_l = (const float*)d_in[2];
    const float* attn_r = (const float*)d_in[3];
    const float* bias   = (const float*)d_in[4];
    const int*   src    = (const int*)d_in[5];
    const int*   dst    = (const int*)d_in[6];
    float* out = (float*)d_out;

    cudaFuncSetAttribute(gemm_hmma_kernel,
                         cudaFuncAttributeMaxDynamicSharedMemorySize, SM_TOTAL);

    // #1: feat fp16 convert + edge count + W transpose
    asplit_w_kernel<<<(N_NODES * IN_FEATS / 4 + 255) / 256, 256>>>(feat, W, dst);
    // #2: persistent GEMM + fused el/er (+ CSR scan in block 0)
    gemm_hmma_kernel<<<GRID_GEMM, 256, SM_TOTAL>>>(attn_l, attn_r);
    // #3: CSR fill + CSR-ordered leaky logits (2 threads/edge)
    fill_logits_kernel<<<625, 512>>>(src, dst);
    // #4: softmax + aggregation (+ counter re-zero for next replay)
    aggregate_kernel<<<N_NODES, 256>>>(bias, out);
}